// round 13
// baseline (speedup 1.0000x reference)
#include <cuda_runtime.h>
#include <cuda_bf16.h>
#include <cstdint>
#include <math.h>

// S4D as 1024 batched small GEMMs on mma.sync (HMMA, sm_80 baseline).
//
// K[h, 64k+j] = Re( sum_n cc_n * (r_n^64)^k * r_n^j ),  r_n = exp(dtA[h,n]).
// Per head:  D[64x64] = A[64 x 128] * B[64 x 128]^T   (bf16, fp32 accum)
//   A[k, 2n+0/1] = (Vr_hi, Vi_hi),  A[k, 64+2n+0/1] = (Vr_lo, Vi_lo),  V = r^(64k)
//   B[j, 2n+0/1] = (Ur_hi, -Ui_hi), B[j, 64+2n+0/1] = (Ur_lo, -Ui_lo), U = cc*r^j
// D = Ahi*Bhi + Ahi*Blo + Alo*Bhi (lo*lo dropped ~2^-18): 12 k16 MMA steps.
//
// R13: XOR-swizzled 256B rows (col ^ ((row&7)<<4)) instead of 272B padded
// rows -> smem 35KB -> exactly 32KB -> 7 CTAs/SM (28 warps) and a SINGLE
// 1024-CTA wave (n_conc=1036). Disjoint bit-fields make the k-chunk offset
// an XOR: colbase(bit4) ^ qo(bits5-6) ^ lohalf(bit7) ^ mask(bits4-6).

#define RST 256   // row stride in bytes (swizzled, no padding)

__device__ __forceinline__ float2 cmul(float2 a, float2 b) {
    return make_float2(fmaf(a.x, b.x, -a.y * b.y), fmaf(a.x, b.y, a.y * b.x));
}
// hi = {bf16rn(x), bf16rn(y)}; lo = packed exact residuals
__device__ __forceinline__ void split_pack(float x, float y, uint32_t& hi, uint32_t& lo) {
    asm("cvt.rn.bf16x2.f32 %0, %1, %2;" : "=r"(hi) : "f"(y), "f"(x));
    uint32_t xh, yh;
    asm("prmt.b32 %0, %1, %2, 0x1054;" : "=r"(xh) : "r"(hi), "r"(0));
    asm("prmt.b32 %0, %1, %2, 0x3254;" : "=r"(yh) : "r"(hi), "r"(0));
    float xr = x - __uint_as_float(xh);
    float yr = y - __uint_as_float(yh);
    asm("cvt.rn.bf16x2.f32 %0, %1, %2;" : "=r"(lo) : "f"(yr), "f"(xr));
}
__device__ __forceinline__ uint32_t smem_u32(const void* p) {
    uint32_t a;
    asm("{ .reg .u64 t; cvta.to.shared.u64 t, %1; cvt.u32.u64 %0, t; }" : "=r"(a) : "l"(p));
    return a;
}
__device__ __forceinline__ void sts32(uint32_t addr, uint32_t v) {
    asm volatile("st.shared.b32 [%0], %1;" :: "r"(addr), "r"(v) : "memory");
}
__device__ __forceinline__ void ldsm4(uint32_t* r, uint32_t addr) {
    asm volatile("ldmatrix.sync.aligned.m8n8.x4.shared.b16 {%0,%1,%2,%3}, [%4];"
                 : "=r"(r[0]), "=r"(r[1]), "=r"(r[2]), "=r"(r[3]) : "r"(addr));
}
__device__ __forceinline__ void mma16816(float* c, const uint32_t* a,
                                         uint32_t b0, uint32_t b1) {
    asm("mma.sync.aligned.m16n8k16.row.col.f32.bf16.bf16.f32 "
        "{%0,%1,%2,%3}, {%4,%5,%6,%7}, {%8,%9}, {%0,%1,%2,%3};"
        : "+f"(c[0]), "+f"(c[1]), "+f"(c[2]), "+f"(c[3])
        : "r"(a[0]), "r"(a[1]), "r"(a[2]), "r"(a[3]), "r"(b0), "r"(b1));
}

__global__ void __launch_bounds__(128, 7)
s4d_mma(float* __restrict__ out,
        const float* __restrict__ C, const float* __restrict__ log_dt,
        const float* __restrict__ lAr, const float* __restrict__ Ai) {
    __shared__ __align__(1024) __nv_bfloat16 sA[64 * 128];  // 16384 B, swizzled
    __shared__ __align__(1024) __nv_bfloat16 sB[64 * 128];  // 16384 B, swizzled

    const int h    = blockIdx.x;
    const int wid  = threadIdx.x >> 5;   // warp: A rows / D k-rows [16wid,16wid+16)
    const int lane = threadIdx.x & 31;   // lane == mode n

    // ---- per-thread constants for mode n = lane (dup across warps) ----
    const int idx = h * 32 + lane;
    float dt = expf(log_dt[h]);
    float ar = -expf(lAr[idx]);
    float ai = Ai[idx];
    float x  = ar * dt, th = ai * dt;
    float sy, cy; sincosf(th, &sy, &cy);
    float ex = expf(x);
    float2 r = make_float2(ex * cy, ex * sy);
    float den  = ar * ar + ai * ai;
    float c2   = 2.0f * C[idx] / den;
    float2 cc  = make_float2(c2 * ((r.x - 1.0f) * ar + r.y * ai),
                             c2 * (r.y * ar - (r.x - 1.0f) * ai));

    // power ladder
    float2 r2  = cmul(r, r),   r4  = cmul(r2, r2);
    float2 r8  = cmul(r4, r4), r16 = cmul(r8, r8);
    float2 r32 = cmul(r16, r16);
    float2 R   = cmul(r32, r32);                 // r^64

    // ---- B march: U[j] = cc * r^j, rows j in [16*wid, 16*wid+16) ----
    // swizzled col for 4B word at col-byte 4*lane, row ro: (4*lane) ^ ((ro&7)<<4)
    {
        float2 u0 = cc;
        if (wid & 1) u0 = cmul(u0, r16);
        if (wid & 2) u0 = cmul(u0, r32);
        float2 u1 = cmul(u0, r);
        uint32_t wrow = smem_u32(sB) + (16 * wid) * RST;
        uint32_t m = 0;                      // ((row&7)<<4), row starts at 16wid (&7==0)
        const uint32_t cb = 4 * lane;        // bits 2-6
        #pragma unroll
        for (int it = 0; it < 8; ++it) {
            uint32_t cs0 = cb ^ m;           // even row
            uint32_t cs1 = cs0 ^ 16;         // odd row: m|16 (m bit4 is 0)
            uint32_t hi, lo;
            split_pack(u0.x, -u0.y, hi, lo);
            sts32(wrow + cs0, hi); sts32(wrow + cs0 + 128, lo);
            split_pack(u1.x, -u1.y, hi, lo);
            sts32(wrow + RST + cs1, hi); sts32(wrow + RST + cs1 + 128, lo);
            u0 = cmul(u0, r2); u1 = cmul(u1, r2);
            wrow += 2 * RST;
            m = (m + 32) & 0x60;             // rows advance by 2: mask cycles 0,32,64,96
        }
    }
    __syncthreads();   // only B crosses warps

    // ---- A march (warp-local): V[k] = R^k, rows k in [16*wid, 16*wid+16) ----
    {
        float2 R2  = cmul(R, R),   R4  = cmul(R2, R2);
        float2 R8  = cmul(R4, R4), R16 = cmul(R8, R8);
        float2 v0 = make_float2(1.0f, 0.0f);
        if (wid & 1) v0 = R16;
        if (wid & 2) {
            float2 R32 = cmul(R16, R16);
            v0 = cmul(v0, R32);
        }
        float2 v1 = cmul(v0, R);
        uint32_t wrow = smem_u32(sA) + (16 * wid) * RST;
        uint32_t m = 0;
        const uint32_t cb = 4 * lane;
        #pragma unroll
        for (int it = 0; it < 8; ++it) {
            uint32_t cs0 = cb ^ m;
            uint32_t cs1 = cs0 ^ 16;
            uint32_t hi, lo;
            split_pack(v0.x, v0.y, hi, lo);
            sts32(wrow + cs0, hi); sts32(wrow + cs0 + 128, lo);
            split_pack(v1.x, v1.y, hi, lo);
            sts32(wrow + RST + cs1, hi); sts32(wrow + RST + cs1 + 128, lo);
            v0 = cmul(v0, R2); v1 = cmul(v1, R2);
            wrow += 2 * RST;
            m = (m + 32) & 0x60;
        }
    }
    __syncwarp();      // A tile produced & consumed by this warp only

    // ---- per-lane ldmatrix base addresses (swizzle folded in) ----
    const uint32_t sA_a = smem_u32(sA), sB_a = smem_u32(sB);
    const int arow = 16 * wid + (lane & 15);
    const uint32_t aAddr = sA_a + arow * RST
                         + (((lane >> 4) * 16) ^ ((arow & 7) << 4));
    const int brow = 8 * (lane >> 4) + (lane & 7);
    const uint32_t bAddr0 = sB_a + brow * RST
                          + ((((lane >> 3) & 1) * 16) ^ ((brow & 7) << 4));

    // ---- mma: warp wid computes D k-rows [16wid,16wid+16) x 64 j-cols ----
    float acc[8][4];
    #pragma unroll
    for (int nt = 0; nt < 8; ++nt)
        #pragma unroll
        for (int e = 0; e < 4; ++e) acc[nt][e] = 0.0f;

    #pragma unroll
    for (int q = 0; q < 4; ++q) {
        const uint32_t qo = 32u * q;           // bits 5-6: XOR == column advance
        uint32_t ah[4], bh[4][4];
        ldsm4(ah, aAddr ^ qo);
        #pragma unroll
        for (int p = 0; p < 4; ++p)
            ldsm4(bh[p], (bAddr0 + p * 16 * RST) ^ qo);
        // t0: ah * bh
        #pragma unroll
        for (int nt = 0; nt < 8; ++nt)
            mma16816(acc[nt], ah, bh[nt >> 1][(nt & 1) * 2], bh[nt >> 1][(nt & 1) * 2 + 1]);
        // t1: ah * bl (two halves to limit register pressure)
        #pragma unroll
        for (int ph = 0; ph < 2; ++ph) {
            uint32_t bl[2][4];
            ldsm4(bl[0], (bAddr0 + (2 * ph)     * 16 * RST) ^ (qo | 128u));
            ldsm4(bl[1], (bAddr0 + (2 * ph + 1) * 16 * RST) ^ (qo | 128u));
            #pragma unroll
            for (int nt = 4 * ph; nt < 4 * ph + 4; ++nt)
                mma16816(acc[nt], ah,
                         bl[(nt >> 1) & 1][(nt & 1) * 2], bl[(nt >> 1) & 1][(nt & 1) * 2 + 1]);
        }
        // t2: al * bh
        {
            uint32_t al[4];
            ldsm4(al, aAddr ^ (qo | 128u));
            #pragma unroll
            for (int nt = 0; nt < 8; ++nt)
                mma16816(acc[nt], al, bh[nt >> 1][(nt & 1) * 2], bh[nt >> 1][(nt & 1) * 2 + 1]);
        }
    }

    // ---- store D: out[h*4096 + k*64 + j], k = 16wid+g(+8), j = 8nt+2tg ----
    const int g  = lane >> 2;
    const int tg = lane & 3;
    float* const ob = out + (size_t)h * 4096 + (16 * wid + g) * 64 + 2 * tg;
    #pragma unroll
    for (int nt = 0; nt < 8; ++nt) {
        float* p = ob + 8 * nt;
        *(float2*)p            = make_float2(acc[nt][0], acc[nt][1]);
        *(float2*)(p + 8 * 64) = make_float2(acc[nt][2], acc[nt][3]);
    }
}

// ---------------- launch ----------------------------------------------------
extern "C" void kernel_launch(void* const* d_in, const int* in_sizes, int n_in,
                              void* d_out, int out_size) {
    const float* C      = (const float*)d_in[0];
    const float* log_dt = (const float*)d_in[1];
    const float* lAr    = (const float*)d_in[2];
    const float* Ai     = (const float*)d_in[3];
    const int H = in_sizes[1];               // 1024

    s4d_mma<<<H, 128>>>((float*)d_out, C, log_dt, lAr, Ai);
}

// round 14
// speedup vs baseline: 1.3208x; 1.3208x over previous
#include <cuda_runtime.h>
#include <cuda_bf16.h>
#include <cstdint>
#include <math.h>

// S4D as 1024 batched small GEMMs on mma.sync (HMMA, sm_80 baseline).
//
// K[h, 64k+j] = Re( sum_n cc_n * (r_n^64)^k * r_n^j ),  r_n = exp(dtA[h,n]).
// Per head:  D[64x64] = A[64 x 128] * B[64 x 128]^T   (bf16, fp32 accum)
//   A[k, 2n+0/1] = (Vr_hi, Vi_hi),  A[k, 64+2n+0/1] = (Vr_lo, Vi_lo),  V = r^(64k)
//   B[j, 2n+0/1] = (Ur_hi, -Ui_hi), B[j, 64+2n+0/1] = (Ur_lo, -Ui_lo), U = cc*r^j
// D = Ahi*Bhi + Ahi*Blo + Alo*Bhi (lo*lo dropped ~2^-18): 12 k16 MMA steps.
//
// R14 = R12 (best measured: padded 272B rows, 6 CTAs/SM) + QUAD-chain
// marches: 4 independent complex chains stepping r^4 / R^4 halve the serial
// FFMA dependency depth of each march and expose 4-wide ILP per iteration.

#define AST 136   // row stride in halves (272B; LDSM conflict-free)
#define BST 136

__device__ __forceinline__ float2 cmul(float2 a, float2 b) {
    return make_float2(fmaf(a.x, b.x, -a.y * b.y), fmaf(a.x, b.y, a.y * b.x));
}
// hi = {bf16rn(x), bf16rn(y)}; lo = packed exact residuals
__device__ __forceinline__ void split_pack(float x, float y, uint32_t& hi, uint32_t& lo) {
    asm("cvt.rn.bf16x2.f32 %0, %1, %2;" : "=r"(hi) : "f"(y), "f"(x));
    uint32_t xh, yh;
    asm("prmt.b32 %0, %1, %2, 0x1054;" : "=r"(xh) : "r"(hi), "r"(0));
    asm("prmt.b32 %0, %1, %2, 0x3254;" : "=r"(yh) : "r"(hi), "r"(0));
    float xr = x - __uint_as_float(xh);
    float yr = y - __uint_as_float(yh);
    asm("cvt.rn.bf16x2.f32 %0, %1, %2;" : "=r"(lo) : "f"(yr), "f"(xr));
}
__device__ __forceinline__ uint32_t smem_u32(const void* p) {
    uint32_t a;
    asm("{ .reg .u64 t; cvta.to.shared.u64 t, %1; cvt.u32.u64 %0, t; }" : "=r"(a) : "l"(p));
    return a;
}
__device__ __forceinline__ void sts32(uint32_t addr, uint32_t v) {
    asm volatile("st.shared.b32 [%0], %1;" :: "r"(addr), "r"(v) : "memory");
}
__device__ __forceinline__ void ldsm4(uint32_t* r, uint32_t addr) {
    asm volatile("ldmatrix.sync.aligned.m8n8.x4.shared.b16 {%0,%1,%2,%3}, [%4];"
                 : "=r"(r[0]), "=r"(r[1]), "=r"(r[2]), "=r"(r[3]) : "r"(addr));
}
__device__ __forceinline__ void mma16816(float* c, const uint32_t* a,
                                         uint32_t b0, uint32_t b1) {
    asm("mma.sync.aligned.m16n8k16.row.col.f32.bf16.bf16.f32 "
        "{%0,%1,%2,%3}, {%4,%5,%6,%7}, {%8,%9}, {%0,%1,%2,%3};"
        : "+f"(c[0]), "+f"(c[1]), "+f"(c[2]), "+f"(c[3])
        : "r"(a[0]), "r"(a[1]), "r"(a[2]), "r"(a[3]), "r"(b0), "r"(b1));
}

__global__ void __launch_bounds__(128, 6)
s4d_mma(float* __restrict__ out,
        const float* __restrict__ C, const float* __restrict__ log_dt,
        const float* __restrict__ lAr, const float* __restrict__ Ai) {
    __shared__ __align__(16) __nv_bfloat16 sA[64 * AST];  // 17408 B
    __shared__ __align__(16) __nv_bfloat16 sB[64 * BST];  // 17408 B

    const int h    = blockIdx.x;
    const int wid  = threadIdx.x >> 5;   // warp: A rows / D k-rows [16wid,16wid+16)
    const int lane = threadIdx.x & 31;   // lane == mode n

    // ---- per-thread constants for mode n = lane (dup across warps) ----
    const int idx = h * 32 + lane;
    float dt = expf(log_dt[h]);
    float ar = -expf(lAr[idx]);
    float ai = Ai[idx];
    float x  = ar * dt, th = ai * dt;
    float sy, cy; sincosf(th, &sy, &cy);
    float ex = expf(x);
    float2 r = make_float2(ex * cy, ex * sy);
    float den  = ar * ar + ai * ai;
    float c2   = 2.0f * C[idx] / den;
    float2 cc  = make_float2(c2 * ((r.x - 1.0f) * ar + r.y * ai),
                             c2 * (r.y * ar - (r.x - 1.0f) * ai));

    // power ladder
    float2 r2  = cmul(r, r),   r4  = cmul(r2, r2);
    float2 r8  = cmul(r4, r4), r16 = cmul(r8, r8);
    float2 r32 = cmul(r16, r16);
    float2 R   = cmul(r32, r32);                 // r^64

    // ---- B march: U[j] = cc * r^j, rows j in [16*wid, 16*wid+16) ----
    // 4 independent chains (rows i mod 4) stepping r^4.
    {
        float2 u[4];
        u[0] = cc;
        if (wid & 1) u[0] = cmul(u[0], r16);
        if (wid & 2) u[0] = cmul(u[0], r32);
        u[1] = cmul(u[0], r);
        u[2] = cmul(u[0], r2);
        u[3] = cmul(u[1], r2);
        uint32_t w = smem_u32(sB) + (16 * wid) * (BST * 2) + 4 * lane;
        #pragma unroll
        for (int it = 0; it < 4; ++it) {
            #pragma unroll
            for (int i = 0; i < 4; ++i) {
                uint32_t hi, lo;
                split_pack(u[i].x, -u[i].y, hi, lo);
                sts32(w + i * (BST * 2), hi);
                sts32(w + i * (BST * 2) + 128, lo);
                u[i] = cmul(u[i], r4);
            }
            w += 4 * (BST * 2);
        }
    }
    __syncthreads();   // only B crosses warps

    // ---- A march (warp-local): V[k] = R^k, rows k in [16*wid, 16*wid+16) ----
    {
        float2 R2  = cmul(R, R),   R4  = cmul(R2, R2);
        float2 R8  = cmul(R4, R4), R16 = cmul(R8, R8);
        float2 v[4];
        v[0] = make_float2(1.0f, 0.0f);
        if (wid & 1) v[0] = R16;
        if (wid & 2) {
            float2 R32 = cmul(R16, R16);
            v[0] = cmul(v[0], R32);
        }
        v[1] = cmul(v[0], R);
        v[2] = cmul(v[0], R2);
        v[3] = cmul(v[1], R2);
        uint32_t w = smem_u32(sA) + (16 * wid) * (AST * 2) + 4 * lane;
        #pragma unroll
        for (int it = 0; it < 4; ++it) {
            #pragma unroll
            for (int i = 0; i < 4; ++i) {
                uint32_t hi, lo;
                split_pack(v[i].x, v[i].y, hi, lo);
                sts32(w + i * (AST * 2), hi);
                sts32(w + i * (AST * 2) + 128, lo);
                v[i] = cmul(v[i], R4);
            }
            w += 4 * (AST * 2);
        }
    }
    __syncwarp();      // A tile produced & consumed by this warp only

    // ---- per-lane ldmatrix base addresses ----
    const uint32_t sA_a = smem_u32(sA), sB_a = smem_u32(sB);
    const uint32_t aAddr = sA_a + (16 * wid + (lane & 15)) * (AST * 2)
                         + (lane >> 4) * 16;
    const uint32_t bAddr0 = sB_a + (8 * (lane >> 4) + (lane & 7)) * (BST * 2)
                          + ((lane >> 3) & 1) * 16;

    // ---- mma: warp wid computes D k-rows [16wid,16wid+16) x 64 j-cols ----
    float acc[8][4];
    #pragma unroll
    for (int nt = 0; nt < 8; ++nt)
        #pragma unroll
        for (int e = 0; e < 4; ++e) acc[nt][e] = 0.0f;

    #pragma unroll
    for (int q = 0; q < 4; ++q) {
        const uint32_t qo = 32u * q;
        uint32_t ah[4], bh[4][4];
        ldsm4(ah, aAddr + qo);
        #pragma unroll
        for (int p = 0; p < 4; ++p)
            ldsm4(bh[p], bAddr0 + p * 16 * (BST * 2) + qo);
        // t0: ah * bh
        #pragma unroll
        for (int nt = 0; nt < 8; ++nt)
            mma16816(acc[nt], ah, bh[nt >> 1][(nt & 1) * 2], bh[nt >> 1][(nt & 1) * 2 + 1]);
        // t1: ah * bl (two halves to limit register pressure)
        #pragma unroll
        for (int ph = 0; ph < 2; ++ph) {
            uint32_t bl[2][4];
            ldsm4(bl[0], bAddr0 + (2 * ph)     * 16 * (BST * 2) + 128u + qo);
            ldsm4(bl[1], bAddr0 + (2 * ph + 1) * 16 * (BST * 2) + 128u + qo);
            #pragma unroll
            for (int nt = 4 * ph; nt < 4 * ph + 4; ++nt)
                mma16816(acc[nt], ah,
                         bl[(nt >> 1) & 1][(nt & 1) * 2], bl[(nt >> 1) & 1][(nt & 1) * 2 + 1]);
        }
        // t2: al * bh
        {
            uint32_t al[4];
            ldsm4(al, aAddr + 128u + qo);
            #pragma unroll
            for (int nt = 0; nt < 8; ++nt)
                mma16816(acc[nt], al, bh[nt >> 1][(nt & 1) * 2], bh[nt >> 1][(nt & 1) * 2 + 1]);
        }
    }

    // ---- store D: out[h*4096 + k*64 + j], k = 16wid+g(+8), j = 8nt+2tg ----
    const int g  = lane >> 2;
    const int tg = lane & 3;
    float* const ob = out + (size_t)h * 4096 + (16 * wid + g) * 64 + 2 * tg;
    #pragma unroll
    for (int nt = 0; nt < 8; ++nt) {
        float* p = ob + 8 * nt;
        *(float2*)p            = make_float2(acc[nt][0], acc[nt][1]);
        *(float2*)(p + 8 * 64) = make_float2(acc[nt][2], acc[nt][3]);
    }
}

// ---------------- launch ----------------------------------------------------
extern "C" void kernel_launch(void* const* d_in, const int* in_sizes, int n_in,
                              void* d_out, int out_size) {
    const float* C      = (const float*)d_in[0];
    const float* log_dt = (const float*)d_in[1];
    const float* lAr    = (const float*)d_in[2];
    const float* Ai     = (const float*)d_in[3];
    const int H = in_sizes[1];               // 1024

    s4d_mma<<<H, 128>>>((float*)d_out, C, log_dt, lAr, Ai);
}

// round 15
// speedup vs baseline: 1.3241x; 1.0025x over previous
#include <cuda_runtime.h>
#include <cuda_bf16.h>
#include <cstdint>
#include <math.h>

// S4D as 1024 batched small GEMMs on mma.sync (HMMA, sm_80 baseline).
//
// K[h, 64k+j] = Re( sum_n cc_n * (r_n^64)^k * r_n^j ),  r_n = exp(dtA[h,n]).
// Per head:  D[64x64] = A[64 x 128] * B[64 x 128]^T   (bf16, fp32 accum)
//   A[k, 2n+0/1] = (Vr_hi, Vi_hi),  A[k, 64+2n+0/1] = (Vr_lo, Vi_lo),  V = r^(64k)
//   B[j, 2n+0/1] = (Ur_hi, -Ui_hi), B[j, 64+2n+0/1] = (Ur_lo, -Ui_lo), U = cc*r^j
// D = Ahi*Bhi + Ahi*Blo + Alo*Bhi (lo*lo dropped ~2^-18): 12 k16 MMA steps.
//
// R15: 256-thread CTA, 8 warps, warp-tile 16k x 32j. Per-warp footprint
// halves (acc 16 regs, march 8+8 rows) -> <=64 regs -> 4 CTAs/SM = 32
// warps/SM (was 24). A is now cross-warp; one __syncthreads covers A+B.

#define AST 136   // row stride in halves (272B; LDSM conflict-free)
#define BST 136

__device__ __forceinline__ float2 cmul(float2 a, float2 b) {
    return make_float2(fmaf(a.x, b.x, -a.y * b.y), fmaf(a.x, b.y, a.y * b.x));
}
// hi = {bf16rn(x), bf16rn(y)}; lo = packed exact residuals
__device__ __forceinline__ void split_pack(float x, float y, uint32_t& hi, uint32_t& lo) {
    asm("cvt.rn.bf16x2.f32 %0, %1, %2;" : "=r"(hi) : "f"(y), "f"(x));
    uint32_t xh, yh;
    asm("prmt.b32 %0, %1, %2, 0x1054;" : "=r"(xh) : "r"(hi), "r"(0));
    asm("prmt.b32 %0, %1, %2, 0x3254;" : "=r"(yh) : "r"(hi), "r"(0));
    float xr = x - __uint_as_float(xh);
    float yr = y - __uint_as_float(yh);
    asm("cvt.rn.bf16x2.f32 %0, %1, %2;" : "=r"(lo) : "f"(yr), "f"(xr));
}
__device__ __forceinline__ uint32_t smem_u32(const void* p) {
    uint32_t a;
    asm("{ .reg .u64 t; cvta.to.shared.u64 t, %1; cvt.u32.u64 %0, t; }" : "=r"(a) : "l"(p));
    return a;
}
__device__ __forceinline__ void sts32(uint32_t addr, uint32_t v) {
    asm volatile("st.shared.b32 [%0], %1;" :: "r"(addr), "r"(v) : "memory");
}
__device__ __forceinline__ void ldsm4(uint32_t* r, uint32_t addr) {
    asm volatile("ldmatrix.sync.aligned.m8n8.x4.shared.b16 {%0,%1,%2,%3}, [%4];"
                 : "=r"(r[0]), "=r"(r[1]), "=r"(r[2]), "=r"(r[3]) : "r"(addr));
}
__device__ __forceinline__ void mma16816(float* c, const uint32_t* a,
                                         uint32_t b0, uint32_t b1) {
    asm("mma.sync.aligned.m16n8k16.row.col.f32.bf16.bf16.f32 "
        "{%0,%1,%2,%3}, {%4,%5,%6,%7}, {%8,%9}, {%0,%1,%2,%3};"
        : "+f"(c[0]), "+f"(c[1]), "+f"(c[2]), "+f"(c[3])
        : "r"(a[0]), "r"(a[1]), "r"(a[2]), "r"(a[3]), "r"(b0), "r"(b1));
}

__global__ void __launch_bounds__(256, 4)
s4d_mma(float* __restrict__ out,
        const float* __restrict__ C, const float* __restrict__ log_dt,
        const float* __restrict__ lAr, const float* __restrict__ Ai) {
    __shared__ __align__(16) __nv_bfloat16 sA[64 * AST];  // 17408 B
    __shared__ __align__(16) __nv_bfloat16 sB[64 * BST];  // 17408 B

    const int h    = blockIdx.x;
    const int wid  = threadIdx.x >> 5;   // 0..7
    const int lane = threadIdx.x & 31;   // lane == mode n

    // ---- per-thread constants for mode n = lane (dup across warps) ----
    const int idx = h * 32 + lane;
    float dt = expf(log_dt[h]);
    float ar = -expf(lAr[idx]);
    float ai = Ai[idx];
    float x  = ar * dt, th = ai * dt;
    float sy, cy; sincosf(th, &sy, &cy);
    float ex = expf(x);
    float2 r = make_float2(ex * cy, ex * sy);
    float den  = ar * ar + ai * ai;
    float c2   = 2.0f * C[idx] / den;
    float2 cc  = make_float2(c2 * ((r.x - 1.0f) * ar + r.y * ai),
                             c2 * (r.y * ar - (r.x - 1.0f) * ai));

    // power ladder (r^2 .. r^64)
    float2 r2  = cmul(r, r),   r4  = cmul(r2, r2);
    float2 r8  = cmul(r4, r4), r16 = cmul(r8, r8);
    float2 r32 = cmul(r16, r16);
    float2 R   = cmul(r32, r32);                 // r^64

    // ---- B march: U[j] = cc * r^j, rows j in [8*wid, 8*wid+8) ----
    {
        float2 u[4];
        u[0] = cc;
        if (wid & 1) u[0] = cmul(u[0], r8);
        if (wid & 2) u[0] = cmul(u[0], r16);
        if (wid & 4) u[0] = cmul(u[0], r32);
        u[1] = cmul(u[0], r);
        u[2] = cmul(u[0], r2);
        u[3] = cmul(u[1], r2);
        uint32_t w = smem_u32(sB) + (8 * wid) * (BST * 2) + 4 * lane;
        #pragma unroll
        for (int it = 0; it < 2; ++it) {
            #pragma unroll
            for (int i = 0; i < 4; ++i) {
                uint32_t hi, lo;
                split_pack(u[i].x, -u[i].y, hi, lo);
                sts32(w + i * (BST * 2), hi);
                sts32(w + i * (BST * 2) + 128, lo);
                u[i] = cmul(u[i], r4);
            }
            w += 4 * (BST * 2);
        }
    }

    // ---- A march: V[k] = R^k, rows k in [8*wid, 8*wid+8) ----
    {
        float2 R2  = cmul(R, R),   R4  = cmul(R2, R2);
        float2 R8  = cmul(R4, R4), R16 = cmul(R8, R8);
        float2 R32 = cmul(R16, R16);
        float2 v[4];
        v[0] = make_float2(1.0f, 0.0f);
        if (wid & 1) v[0] = R8;
        if (wid & 2) v[0] = cmul(v[0], R16);
        if (wid & 4) v[0] = cmul(v[0], R32);
        v[1] = cmul(v[0], R);
        v[2] = cmul(v[0], R2);
        v[3] = cmul(v[1], R2);
        uint32_t w = smem_u32(sA) + (8 * wid) * (AST * 2) + 4 * lane;
        #pragma unroll
        for (int it = 0; it < 2; ++it) {
            #pragma unroll
            for (int i = 0; i < 4; ++i) {
                uint32_t hi, lo;
                split_pack(v[i].x, v[i].y, hi, lo);
                sts32(w + i * (AST * 2), hi);
                sts32(w + i * (AST * 2) + 128, lo);
                v[i] = cmul(v[i], R4);
            }
            w += 4 * (AST * 2);
        }
    }
    __syncthreads();   // A and B both cross warps now

    // ---- warp tile: kk = wid>>1 (k-rows 16kk..+16), jj = wid&1 (j 32jj..+32) ----
    const int kk = wid >> 1;
    const int jj = wid & 1;
    const uint32_t sA_a = smem_u32(sA), sB_a = smem_u32(sB);
    const uint32_t aAddr  = sA_a + (16 * kk + (lane & 15)) * (AST * 2)
                          + (lane >> 4) * 16;
    const uint32_t bAddr0 = sB_a + (32 * jj + 8 * (lane >> 4) + (lane & 7)) * (BST * 2)
                          + ((lane >> 3) & 1) * 16;

    float acc[4][4];
    #pragma unroll
    for (int nt = 0; nt < 4; ++nt)
        #pragma unroll
        for (int e = 0; e < 4; ++e) acc[nt][e] = 0.0f;

    #pragma unroll
    for (int q = 0; q < 4; ++q) {
        const uint32_t qo = 32u * q;
        uint32_t ah[4], bh[2][4];
        ldsm4(ah, aAddr + qo);
        ldsm4(bh[0], bAddr0 + qo);
        ldsm4(bh[1], bAddr0 + 16 * (BST * 2) + qo);
        // t0: ah * bh
        #pragma unroll
        for (int nt = 0; nt < 4; ++nt)
            mma16816(acc[nt], ah, bh[nt >> 1][(nt & 1) * 2], bh[nt >> 1][(nt & 1) * 2 + 1]);
        // t1: ah * bl
        {
            uint32_t bl[2][4];
            ldsm4(bl[0], bAddr0 + 128u + qo);
            ldsm4(bl[1], bAddr0 + 16 * (BST * 2) + 128u + qo);
            #pragma unroll
            for (int nt = 0; nt < 4; ++nt)
                mma16816(acc[nt], ah, bl[nt >> 1][(nt & 1) * 2], bl[nt >> 1][(nt & 1) * 2 + 1]);
        }
        // t2: al * bh
        {
            uint32_t al[4];
            ldsm4(al, aAddr + 128u + qo);
            #pragma unroll
            for (int nt = 0; nt < 4; ++nt)
                mma16816(acc[nt], al, bh[nt >> 1][(nt & 1) * 2], bh[nt >> 1][(nt & 1) * 2 + 1]);
        }
    }

    // ---- store D: rows 16kk+g (+8), cols 32jj + 8nt + 2tg ----
    const int g  = lane >> 2;
    const int tg = lane & 3;
    float* const ob = out + (size_t)h * 4096 + (16 * kk + g) * 64 + 32 * jj + 2 * tg;
    #pragma unroll
    for (int nt = 0; nt < 4; ++nt) {
        float* p = ob + 8 * nt;
        *(float2*)p            = make_float2(acc[nt][0], acc[nt][1]);
        *(float2*)(p + 8 * 64) = make_float2(acc[nt][2], acc[nt][3]);
    }
}

// ---------------- launch ----------------------------------------------------
extern "C" void kernel_launch(void* const* d_in, const int* in_sizes, int n_in,
                              void* d_out, int out_size) {
    const float* C      = (const float*)d_in[0];
    const float* log_dt = (const float*)d_in[1];
    const float* lAr    = (const float*)d_in[2];
    const float* Ai     = (const float*)d_in[3];
    const int H = in_sizes[1];               // 1024

    s4d_mma<<<H, 256>>>((float*)d_out, C, log_dt, lAr, Ai);
}